// round 15
// baseline (speedup 1.0000x reference)
#include <cuda_runtime.h>

#define NMAX   100000
#define EMAX   1600000
#define INH    18
#define OUTH   11
#define OUTP   12      // 11 features + dinv in slot 11
#define NCLASS 40
#define CDIM   51      // NCLASS + OUTH
#define NBLK   98      // ceil(NMAX/1024)

// ---------------- scratch (device globals; zero-init BSS) ----------------
__device__ int   g_cnt   [NMAX];       // in-degree; re-zeroed in agg1 phase
__device__ int   g_rowptr[NMAX];       // block-local excl scan; bumped by scatter
__device__ int   g_blksum[NBLK];
__device__ int   g_blkoff[NBLK];
__device__ float g_dinv[NMAX];
__device__ float g_sdin[NMAX];
__device__ __align__(16) float g_M  [NMAX * OUTP];   // [m0..m10, dinv]
__device__ __align__(16) float g_Y1 [NMAX * OUTP];   // [y0..y10, dinv]
__device__ __align__(16) float g_Y2 [NMAX * OUTP];
__device__ int   g_esrc[EMAX];         // CSR src ids (dst-major)
__device__ float g_c  [OUTH];          // b1 @ W2
__device__ int   g_barcnt;             // barrier arrivals (self-resetting)
__device__ int   g_bargen;             // barrier generation (monotonic)

// device-wide barrier; safe because grid <= resident capacity
__device__ __forceinline__ void gsync() {
    __syncthreads();
    if (threadIdx.x == 0) {
        __threadfence();
        int gen = atomicAdd(&g_bargen, 0);
        if (atomicAdd(&g_barcnt, 1) == (int)gridDim.x - 1) {
            atomicExch(&g_barcnt, 0);
            __threadfence();
            atomicAdd(&g_bargen, 1);
        } else {
            while (atomicAdd(&g_bargen, 0) == gen) __nanosleep(64);
        }
    }
    __syncthreads();
}

// ---------------- the persistent mega-kernel ----------------
__global__ void __launch_bounds__(256) k_mega(
    const float* __restrict__ x, const int* __restrict__ ei,
    const float* __restrict__ emb_a,
    const float* __restrict__ W1, const float* __restrict__ b1,
    const float* __restrict__ W2, const float* __restrict__ b2,
    const float* __restrict__ Wc, const float* __restrict__ bc,
    float* __restrict__ out, int n, int e, int nh)
{
    __shared__ int   sh[256];
    __shared__ int   sh2[128];
    __shared__ float w[INH * OUTH];
    __shared__ float wsm[CDIM * NCLASS];
    __shared__ float bsm[NCLASS];
    __shared__ float csm[OUTH];
    __shared__ float b2sm[OUTH];

    const int t    = threadIdx.x;
    const int gtid = blockIdx.x * blockDim.x + t;
    const int GT   = gridDim.x * blockDim.x;
    const int nblk = (n + 1023) / 1024;
    const int nth4 = (e + 3) >> 2;            // edge chunks of 4

    // ================= phase A: in-degree histogram =================
    const int* dst = ei + e;
    for (int i = gtid; i < nth4; i += GT) {
        int base = i * 4;
        if ((e & 3) == 0 || base + 3 < e) {
            int4 d4 = *reinterpret_cast<const int4*>(dst + base);
            atomicAdd(&g_cnt[d4.x], 1);
            atomicAdd(&g_cnt[d4.y], 1);
            atomicAdd(&g_cnt[d4.z], 1);
            atomicAdd(&g_cnt[d4.w], 1);
        } else {
            for (int k = base; k < e; k++) atomicAdd(&g_cnt[dst[k]], 1);
        }
    }
    gsync();

    // ================= phase B1: block-local scans + dinv =================
    for (int vb = blockIdx.x; vb < nblk; vb += gridDim.x) {
        int base = vb * 1024 + t * 4;
        int v0 = 0, v1 = 0, v2 = 0, v3 = 0;
        if (base + 3 < n) {
            int4 c = *reinterpret_cast<const int4*>(&g_cnt[base]);
            v0 = c.x; v1 = c.y; v2 = c.z; v3 = c.w;
        } else {
            if (base     < n) v0 = g_cnt[base];
            if (base + 1 < n) v1 = g_cnt[base + 1];
            if (base + 2 < n) v2 = g_cnt[base + 2];
            if (base + 3 < n) v3 = g_cnt[base + 3];
        }
        int tsum = v0 + v1 + v2 + v3;
        sh[t] = tsum;
        __syncthreads();
        for (int off = 1; off < 256; off <<= 1) {
            int xx = (t >= off) ? sh[t - off] : 0;
            __syncthreads();
            sh[t] += xx;
            __syncthreads();
        }
        int excl = sh[t] - tsum;
        if (t == 255) g_blksum[vb] = sh[255];
        if (base     < n) { g_rowptr[base]     = excl;                g_dinv[base]     = rsqrtf((float)(v0 + 1)); }
        if (base + 1 < n) { g_rowptr[base + 1] = excl + v0;           g_dinv[base + 1] = rsqrtf((float)(v1 + 1)); }
        if (base + 2 < n) { g_rowptr[base + 2] = excl + v0 + v1;      g_dinv[base + 2] = rsqrtf((float)(v2 + 1)); }
        if (base + 3 < n) { g_rowptr[base + 3] = excl + v0 + v1 + v2; g_dinv[base + 3] = rsqrtf((float)(v3 + 1)); }
        __syncthreads();
    }
    // c = b1 @ W2 (one block)
    if (blockIdx.x == 0 && t < OUTH) {
        float s = 0.f;
        for (int k = 0; k < nh; k++) s += b1[k] * W2[k * OUTH + t];
        g_c[t] = s;
    }
    gsync();

    // ================= phase B2: top-level scan of block sums =================
    if (blockIdx.x == 0) {
        int v = 0;
        if (t < nblk) v = g_blksum[t];
        if (t < 128) sh2[t] = (t < nblk) ? v : 0;
        __syncthreads();
        for (int off = 1; off < 128; off <<= 1) {
            int xx = 0;
            if (t < 128 && t >= off) xx = sh2[t - off];
            __syncthreads();
            if (t < 128) sh2[t] += xx;
            __syncthreads();
        }
        if (t < nblk) g_blkoff[t] = sh2[t] - v;   // exclusive
    }
    gsync();

    // ================= phase C: scatter (CSR build) + M = x@W12 =================
    for (int i = gtid; i < nth4; i += GT) {
        int base = i * 4;
        if ((e & 3) == 0 || base + 3 < e) {
            int4 s4 = *reinterpret_cast<const int4*>(ei + base);
            int4 d4 = *reinterpret_cast<const int4*>(ei + e + base);
            int p;
            p = atomicAdd(&g_rowptr[d4.x], 1) + g_blkoff[d4.x >> 10]; g_esrc[p] = s4.x;
            p = atomicAdd(&g_rowptr[d4.y], 1) + g_blkoff[d4.y >> 10]; g_esrc[p] = s4.y;
            p = atomicAdd(&g_rowptr[d4.z], 1) + g_blkoff[d4.z >> 10]; g_esrc[p] = s4.z;
            p = atomicAdd(&g_rowptr[d4.w], 1) + g_blkoff[d4.w >> 10]; g_esrc[p] = s4.w;
        } else {
            for (int k = base; k < e; k++) {
                int s = ei[k], d = ei[e + k];
                int p = atomicAdd(&g_rowptr[d], 1) + g_blkoff[d >> 10];
                g_esrc[p] = s;
            }
        }
    }
    __syncthreads();
    if (t < INH * OUTH) {               // W12 per block
        int i = t / OUTH, j = t % OUTH;
        float s = 0.f;
        for (int k = 0; k < nh; k++) s += W1[i * nh + k] * W2[k * OUTH + j];
        w[t] = s;
    }
    __syncthreads();
    for (int node = gtid; node < n; node += GT) {
        float di = g_dinv[node];
        float xr[INH];
#pragma unroll
        for (int k = 0; k < INH; k++) xr[k] = x[node * INH + k];
        float o[OUTP];
#pragma unroll
        for (int j = 0; j < OUTH; j++) {
            float s = 0.f;
#pragma unroll
            for (int k = 0; k < INH; k++) s += xr[k] * w[k * OUTH + j];
            o[j] = s;
        }
        o[OUTH] = di;                   // pack dinv in slot 11
        float4* mp = reinterpret_cast<float4*>(&g_M[node * OUTP]);
        mp[0] = make_float4(o[0], o[1], o[2],  o[3]);
        mp[1] = make_float4(o[4], o[5], o[6],  o[7]);
        mp[2] = make_float4(o[8], o[9], o[10], o[11]);
    }
    gsync();

    // ================= phase D: agg0 (4 lanes/node, paired pipeline) =================
    for (int tt = gtid; tt < n * 4; tt += GT) {
        int node = tt >> 2;
        int lane = tt & 3;
        unsigned gmask = 0xFu << (t & 28);
        int   cnt = g_cnt[node];
        int   beg = g_rowptr[node] + g_blkoff[node >> 10] - cnt;  // rowptr was bumped
        float dd  = g_dinv[node];
        float4 acc = make_float4(0.f, 0.f, 0.f, 0.f);
        float  sds = 0.f;
        int k = 0;
        if ((beg & 1) && cnt > 0) {
            int s = __ldg(&g_esrc[beg]);
            float4 v = make_float4(0.f, 0.f, 0.f, 0.f);
            if (lane < 3) v = __ldg(reinterpret_cast<const float4*>(&g_M[s * OUTP]) + lane);
            float ds = __shfl_sync(gmask, v.w, 2, 4);
            acc.x += ds * v.x; acc.y += ds * v.y;
            acc.z += ds * v.z; acc.w += ds * v.w;
            sds += ds;
            k = 1;
        }
        int pairs = (cnt - k) >> 1;
        const int2* ep = reinterpret_cast<const int2*>(&g_esrc[beg + k]);
#pragma unroll 2
        for (int p = 0; p < pairs; p++) {
            int2 ss = __ldg(&ep[p]);
            float4 v0 = make_float4(0.f, 0.f, 0.f, 0.f);
            float4 v1 = make_float4(0.f, 0.f, 0.f, 0.f);
            if (lane < 3) {
                v0 = __ldg(reinterpret_cast<const float4*>(&g_M[ss.x * OUTP]) + lane);
                v1 = __ldg(reinterpret_cast<const float4*>(&g_M[ss.y * OUTP]) + lane);
            }
            float ds0 = __shfl_sync(gmask, v0.w, 2, 4);
            float ds1 = __shfl_sync(gmask, v1.w, 2, 4);
            acc.x += ds0 * v0.x + ds1 * v1.x;
            acc.y += ds0 * v0.y + ds1 * v1.y;
            acc.z += ds0 * v0.z + ds1 * v1.z;
            acc.w += ds0 * v0.w + ds1 * v1.w;
            sds += ds0 + ds1;
        }
        k += pairs * 2;
        if (k < cnt) {
            int s = __ldg(&g_esrc[beg + k]);
            float4 v = make_float4(0.f, 0.f, 0.f, 0.f);
            if (lane < 3) v = __ldg(reinterpret_cast<const float4*>(&g_M[s * OUTP]) + lane);
            float ds = __shfl_sync(gmask, v.w, 2, 4);
            acc.x += ds * v.x; acc.y += ds * v.y;
            acc.z += ds * v.z; acc.w += ds * v.w;
            sds += ds;
        }
        if (lane < 3) {
            float4 m = *(reinterpret_cast<const float4*>(&g_M[node * OUTP]) + lane);
            float4 y;
            y.x = dd * (dd * m.x + acc.x);
            y.y = dd * (dd * m.y + acc.y);
            y.z = dd * (dd * m.z + acc.z);
            y.w = dd * (dd * m.w + acc.w);
            if (lane == 2) y.w = dd;     // keep dinv packed in Y1 slot 11
            *(reinterpret_cast<float4*>(&g_Y1[node * OUTP]) + lane) = y;
        } else {
            g_sdin[node] = sds;
        }
    }
    gsync();

    // ================= phase E: agg1 (Y1 -> Y2); zero cnt for replay =================
    for (int tt = gtid; tt < n * 4; tt += GT) {
        int node = tt >> 2;
        int lane = tt & 3;
        unsigned gmask = 0xFu << (t & 28);
        int   cnt = g_cnt[node];
        int   beg = g_rowptr[node] + g_blkoff[node >> 10] - cnt;
        float dd  = g_dinv[node];
        float4 acc = make_float4(0.f, 0.f, 0.f, 0.f);
        int k = 0;
        if ((beg & 1) && cnt > 0) {
            int s = __ldg(&g_esrc[beg]);
            float4 v = make_float4(0.f, 0.f, 0.f, 0.f);
            if (lane < 3) v = __ldg(reinterpret_cast<const float4*>(&g_Y1[s * OUTP]) + lane);
            float ds = __shfl_sync(gmask, v.w, 2, 4);
            acc.x += ds * v.x; acc.y += ds * v.y;
            acc.z += ds * v.z; acc.w += ds * v.w;
            k = 1;
        }
        int pairs = (cnt - k) >> 1;
        const int2* ep = reinterpret_cast<const int2*>(&g_esrc[beg + k]);
#pragma unroll 2
        for (int p = 0; p < pairs; p++) {
            int2 ss = __ldg(&ep[p]);
            float4 v0 = make_float4(0.f, 0.f, 0.f, 0.f);
            float4 v1 = make_float4(0.f, 0.f, 0.f, 0.f);
            if (lane < 3) {
                v0 = __ldg(reinterpret_cast<const float4*>(&g_Y1[ss.x * OUTP]) + lane);
                v1 = __ldg(reinterpret_cast<const float4*>(&g_Y1[ss.y * OUTP]) + lane);
            }
            float ds0 = __shfl_sync(gmask, v0.w, 2, 4);
            float ds1 = __shfl_sync(gmask, v1.w, 2, 4);
            acc.x += ds0 * v0.x + ds1 * v1.x;
            acc.y += ds0 * v0.y + ds1 * v1.y;
            acc.z += ds0 * v0.z + ds1 * v1.z;
            acc.w += ds0 * v0.w + ds1 * v1.w;
        }
        k += pairs * 2;
        if (k < cnt) {
            int s = __ldg(&g_esrc[beg + k]);
            float4 v = make_float4(0.f, 0.f, 0.f, 0.f);
            if (lane < 3) v = __ldg(reinterpret_cast<const float4*>(&g_Y1[s * OUTP]) + lane);
            float ds = __shfl_sync(gmask, v.w, 2, 4);
            acc.x += ds * v.x; acc.y += ds * v.y;
            acc.z += ds * v.z; acc.w += ds * v.w;
        }
        if (lane < 3) {
            float4 y1 = *(reinterpret_cast<const float4*>(&g_Y1[node * OUTP]) + lane);
            float4 y;
            y.x = dd * (dd * y1.x + acc.x);
            y.y = dd * (dd * y1.y + acc.y);
            y.z = dd * (dd * y1.z + acc.z);
            y.w = dd * (dd * y1.w + acc.w);
            *(reinterpret_cast<float4*>(&g_Y2[node * OUTP]) + lane) = y;
        } else {
            g_cnt[node] = 0;             // replay invariant
        }
    }
    gsync();

    // ================= phase F: epilogue GEMM (2 threads/node) =================
    for (int i = t; i < CDIM * NCLASS; i += blockDim.x) wsm[i] = Wc[i];
    if (t < NCLASS) bsm[t] = bc[t];
    if (t < OUTH) { csm[t] = g_c[t]; b2sm[t] = b2[t]; }
    __syncthreads();
    for (int tt = gtid; tt < n * 2; tt += GT) {
        int node = tt >> 1;
        int colb = (tt & 1) * 20;
        float acc[20];
#pragma unroll
        for (int q = 0; q < 20; q++) acc[q] = bsm[colb + q];

        const float4* ea = reinterpret_cast<const float4*>(&emb_a[(size_t)node * NCLASS]);
#pragma unroll
        for (int m4 = 0; m4 < NCLASS / 4; m4++) {
            float4 v = __ldg(&ea[m4]);
            float vv[4] = {v.x, v.y, v.z, v.w};
#pragma unroll
            for (int c = 0; c < 4; c++) {
                float a = vv[c];
                int m = m4 * 4 + c;
#pragma unroll
                for (int q = 0; q < 20; q++) acc[q] += a * wsm[m * NCLASS + colb + q];
            }
        }
        float di = g_dinv[node];
        float s = di * (di + g_sdin[node]);
#pragma unroll
        for (int j = 0; j < OUTH; j++) {
            float h = g_Y2[(size_t)node * OUTP + j] + s * csm[j] + b2sm[j];
            h = fmaxf(h, 0.0f);
#pragma unroll
            for (int q = 0; q < 20; q++) acc[q] += h * wsm[(NCLASS + j) * NCLASS + colb + q];
        }
        float4* op = reinterpret_cast<float4*>(&out[(size_t)node * NCLASS + colb]);
#pragma unroll
        for (int q4 = 0; q4 < 5; q4++)
            op[q4] = make_float4(acc[q4 * 4], acc[q4 * 4 + 1], acc[q4 * 4 + 2], acc[q4 * 4 + 3]);
    }
}

// ---------------- launch ----------------
extern "C" void kernel_launch(void* const* d_in, const int* in_sizes, int n_in,
                              void* d_out, int out_size) {
    const float* x     = (const float*)d_in[0];
    const int*   ei    = (const int*)d_in[1];     // int32 (JAX x64 disabled)
    const float* emb_a = (const float*)d_in[2];
    const float* W1    = (const float*)d_in[3];
    const float* b1    = (const float*)d_in[4];
    const float* W2    = (const float*)d_in[5];
    const float* b2    = (const float*)d_in[6];
    const float* Wc    = (const float*)d_in[7];
    const float* bc    = (const float*)d_in[8];
    float* out = (float*)d_out;

    int n  = in_sizes[0] / INH;   // 100000
    int e  = in_sizes[1] / 2;     // 1600000
    int nh = in_sizes[4];         // 256

    int dev = 0;
    cudaGetDevice(&dev);
    int sms = 148;
    cudaDeviceGetAttribute(&sms, cudaDevAttrMultiProcessorCount, dev);
    int nb = 0;
    cudaOccupancyMaxActiveBlocksPerMultiprocessor(&nb, k_mega, 256, 0);
    if (nb < 1) nb = 1;
    int grid = sms * nb;          // all blocks resident -> gsync is safe

    k_mega<<<grid, 256>>>(x, ei, emb_a, W1, b1, W2, b2, Wc, bc, out, n, e, nh);
}

// round 16
// speedup vs baseline: 1.7025x; 1.7025x over previous
#include <cuda_runtime.h>

#define NMAX   100000
#define EMAX   1600000
#define INH    18
#define OUTH   11
#define OUTP   12      // 11 features + dinv in slot 11
#define NCLASS 40
#define CDIM   51      // NCLASS + OUTH
#define NBLK   98      // ceil(NMAX/1024)

// ---------------- scratch (device globals; zero-init BSS) ----------------
__device__ int   g_cnt   [NMAX];       // in-degree; re-zeroed by agg1 each run
__device__ int   g_rowptr[NMAX];       // block-local excl scan; bumped by scatter
__device__ int   g_blksum[NBLK];
__device__ int   g_blkoff[NBLK];
__device__ int   g_ctr;                // ticket; reset by scanM last block
__device__ float g_dinv[NMAX];
__device__ float g_sdin[NMAX];
__device__ __align__(16) float g_M  [NMAX * OUTP];   // [m0..m10, dinv]
__device__ __align__(16) float g_Y1 [NMAX * OUTP];   // [y0..y10, dinv]
__device__ __align__(16) float g_Y2 [NMAX * OUTP];
__device__ int   g_esrc[EMAX];         // CSR src ids (dst-major)
__device__ float g_c  [OUTH];          // b1 @ W2

// ---------------- kernels ----------------

// 0: in-degree histogram, 4 edges/thread
__global__ void k_deg(const int* __restrict__ dst, int e) {
    int i = blockIdx.x * blockDim.x + threadIdx.x;
    int base = i * 4;
    if ((e & 3) == 0 && base + 3 < e) {
        int4 d4 = *reinterpret_cast<const int4*>(dst + base);
        atomicAdd(&g_cnt[d4.x], 1);
        atomicAdd(&g_cnt[d4.y], 1);
        atomicAdd(&g_cnt[d4.z], 1);
        atomicAdd(&g_cnt[d4.w], 1);
    } else {
        for (int k = base; k < e && k < base + 4; k++) atomicAdd(&g_cnt[dst[k]], 1);
    }
}

// 1: fused: block-local scan of cnt -> rowptr; W12; dinv+M; last block scans blksums
__global__ void k_scanM(const float* __restrict__ x,
                        const float* __restrict__ W1, const float* __restrict__ W2,
                        const float* __restrict__ b1, int nh, int n) {
    __shared__ float w[INH * OUTH];
    __shared__ int   sh[256];
    __shared__ int   sh2[128];
    __shared__ int   lastblk;
    int b = blockIdx.x, t = threadIdx.x;
    int base = b * 1024 + t * 4;

    int v0 = 0, v1 = 0, v2 = 0, v3 = 0;
    if (base + 3 < n) {
        int4 c = *reinterpret_cast<const int4*>(&g_cnt[base]);
        v0 = c.x; v1 = c.y; v2 = c.z; v3 = c.w;
    } else {
        if (base     < n) v0 = g_cnt[base];
        if (base + 1 < n) v1 = g_cnt[base + 1];
        if (base + 2 < n) v2 = g_cnt[base + 2];
        if (base + 3 < n) v3 = g_cnt[base + 3];
    }
    int tsum = v0 + v1 + v2 + v3;
    sh[t] = tsum;
    __syncthreads();
    for (int off = 1; off < 256; off <<= 1) {
        int xx = (t >= off) ? sh[t - off] : 0;
        __syncthreads();
        sh[t] += xx;
        __syncthreads();
    }
    int excl = sh[t] - tsum;
    if (t == 255) g_blksum[b] = sh[255];
    if (base     < n) g_rowptr[base]     = excl;
    if (base + 1 < n) g_rowptr[base + 1] = excl + v0;
    if (base + 2 < n) g_rowptr[base + 2] = excl + v0 + v1;
    if (base + 3 < n) g_rowptr[base + 3] = excl + v0 + v1 + v2;

    if (t < INH * OUTH) {
        int i = t / OUTH, j = t % OUTH;
        float s = 0.f;
        for (int k = 0; k < nh; k++) s += W1[i * nh + k] * W2[k * OUTH + j];
        w[t] = s;
    } else if (b == 0 && t < INH * OUTH + OUTH) {
        int j = t - INH * OUTH;
        float s = 0.f;
        for (int k = 0; k < nh; k++) s += b1[k] * W2[k * OUTH + j];
        g_c[j] = s;
    }
    __syncthreads();

    int cn[4] = {v0, v1, v2, v3};
#pragma unroll
    for (int q = 0; q < 4; q++) {
        int node = base + q;
        if (node >= n) break;
        float di = rsqrtf((float)(cn[q] + 1));
        g_dinv[node] = di;
        float xr[INH];
#pragma unroll
        for (int k = 0; k < INH; k++) xr[k] = x[node * INH + k];
        float o[OUTP];
#pragma unroll
        for (int j = 0; j < OUTH; j++) {
            float s = 0.f;
#pragma unroll
            for (int k = 0; k < INH; k++) s += xr[k] * w[k * OUTH + j];
            o[j] = s;
        }
        o[OUTH] = di;
        float4* mp = reinterpret_cast<float4*>(&g_M[node * OUTP]);
        mp[0] = make_float4(o[0], o[1], o[2],  o[3]);
        mp[1] = make_float4(o[4], o[5], o[6],  o[7]);
        mp[2] = make_float4(o[8], o[9], o[10], o[11]);
    }

    __syncthreads();
    if (t == 0) {
        __threadfence();
        lastblk = (atomicAdd(&g_ctr, 1) == gridDim.x - 1) ? 1 : 0;
    }
    __syncthreads();
    if (lastblk) {
        __threadfence();
        int v = 0;
        if (t < NBLK) v = g_blksum[t];
        if (t < 128) sh2[t] = (t < NBLK) ? v : 0;
        __syncthreads();
        for (int off = 1; off < 128; off <<= 1) {
            int xx = 0;
            if (t < 128 && t >= off) xx = sh2[t - off];
            __syncthreads();
            if (t < 128) sh2[t] += xx;
            __syncthreads();
        }
        if (t < NBLK) g_blkoff[t] = sh2[t] - v;
        if (t == 0) g_ctr = 0;
    }
}

// 2: scatter src into CSR (atomic directly on rowptr)
__global__ void k_scatter(const int* __restrict__ ei, int e) {
    int i = blockIdx.x * blockDim.x + threadIdx.x;
    int base = i * 4;
    if ((e & 3) == 0 && base + 3 < e) {
        int4 s4 = *reinterpret_cast<const int4*>(ei + base);
        int4 d4 = *reinterpret_cast<const int4*>(ei + e + base);
        int p;
        p = atomicAdd(&g_rowptr[d4.x], 1) + g_blkoff[d4.x >> 10]; g_esrc[p] = s4.x;
        p = atomicAdd(&g_rowptr[d4.y], 1) + g_blkoff[d4.y >> 10]; g_esrc[p] = s4.y;
        p = atomicAdd(&g_rowptr[d4.z], 1) + g_blkoff[d4.z >> 10]; g_esrc[p] = s4.z;
        p = atomicAdd(&g_rowptr[d4.w], 1) + g_blkoff[d4.w >> 10]; g_esrc[p] = s4.w;
    } else {
        for (int k = base; k < e && k < base + 4; k++) {
            int s = ei[k], d = ei[e + k];
            int p = atomicAdd(&g_rowptr[d], 1) + g_blkoff[d >> 10];
            g_esrc[p] = s;
        }
    }
}

// 3: 4 lanes/node, paired-edge pipeline (NO launch_bounds: 36 regs measured best).
//    Y1 = dd*(dd*M + sum ds*M[s]); slot11 = dd; sdin = sum ds (lane 3)
__global__ void k_agg0(int n) {
    int tid  = blockIdx.x * blockDim.x + threadIdx.x;
    int node = tid >> 2;
    int lane = tid & 3;
    if (node >= n) return;
    unsigned gmask = 0xFu << (threadIdx.x & 28);
    int   cnt = g_cnt[node];
    int   beg = g_rowptr[node] + g_blkoff[node >> 10] - cnt;  // rowptr was bumped
    float dd  = g_dinv[node];
    float4 acc = make_float4(0.f, 0.f, 0.f, 0.f);
    float  sds = 0.f;
    int k = 0;
    if ((beg & 1) && cnt > 0) {                 // peel to align int2 loads
        int s = __ldg(&g_esrc[beg]);
        float4 v = make_float4(0.f, 0.f, 0.f, 0.f);
        if (lane < 3) v = __ldg(reinterpret_cast<const float4*>(&g_M[s * OUTP]) + lane);
        float ds = __shfl_sync(gmask, v.w, 2, 4);
        acc.x += ds * v.x; acc.y += ds * v.y;
        acc.z += ds * v.z; acc.w += ds * v.w;
        sds += ds;
        k = 1;
    }
    int pairs = (cnt - k) >> 1;
    const int2* ep = reinterpret_cast<const int2*>(&g_esrc[beg + k]);
#pragma unroll 2
    for (int p = 0; p < pairs; p++) {
        int2 ss = __ldg(&ep[p]);
        float4 v0 = make_float4(0.f, 0.f, 0.f, 0.f);
        float4 v1 = make_float4(0.f, 0.f, 0.f, 0.f);
        if (lane < 3) {
            v0 = __ldg(reinterpret_cast<const float4*>(&g_M[ss.x * OUTP]) + lane);
            v1 = __ldg(reinterpret_cast<const float4*>(&g_M[ss.y * OUTP]) + lane);
        }
        float ds0 = __shfl_sync(gmask, v0.w, 2, 4);
        float ds1 = __shfl_sync(gmask, v1.w, 2, 4);
        acc.x += ds0 * v0.x + ds1 * v1.x;
        acc.y += ds0 * v0.y + ds1 * v1.y;
        acc.z += ds0 * v0.z + ds1 * v1.z;
        acc.w += ds0 * v0.w + ds1 * v1.w;
        sds += ds0 + ds1;
    }
    k += pairs * 2;
    if (k < cnt) {                              // tail edge
        int s = __ldg(&g_esrc[beg + k]);
        float4 v = make_float4(0.f, 0.f, 0.f, 0.f);
        if (lane < 3) v = __ldg(reinterpret_cast<const float4*>(&g_M[s * OUTP]) + lane);
        float ds = __shfl_sync(gmask, v.w, 2, 4);
        acc.x += ds * v.x; acc.y += ds * v.y;
        acc.z += ds * v.z; acc.w += ds * v.w;
        sds += ds;
    }
    if (lane < 3) {
        float4 m = *(reinterpret_cast<const float4*>(&g_M[node * OUTP]) + lane);
        float4 y;
        y.x = dd * (dd * m.x + acc.x);
        y.y = dd * (dd * m.y + acc.y);
        y.z = dd * (dd * m.z + acc.z);
        y.w = dd * (dd * m.w + acc.w);
        if (lane == 2) y.w = dd;         // keep dinv packed in Y1 slot 11
        *(reinterpret_cast<float4*>(&g_Y1[node * OUTP]) + lane) = y;
    } else {
        g_sdin[node] = sds;
    }
}

// 4: same pipeline on Y1 -> Y2; zero cnt for next run
__global__ void k_agg1(int n) {
    int tid  = blockIdx.x * blockDim.x + threadIdx.x;
    int node = tid >> 2;
    int lane = tid & 3;
    if (node >= n) return;
    unsigned gmask = 0xFu << (threadIdx.x & 28);
    int   cnt = g_cnt[node];
    int   beg = g_rowptr[node] + g_blkoff[node >> 10] - cnt;
    float dd  = g_dinv[node];
    float4 acc = make_float4(0.f, 0.f, 0.f, 0.f);
    int k = 0;
    if ((beg & 1) && cnt > 0) {
        int s = __ldg(&g_esrc[beg]);
        float4 v = make_float4(0.f, 0.f, 0.f, 0.f);
        if (lane < 3) v = __ldg(reinterpret_cast<const float4*>(&g_Y1[s * OUTP]) + lane);
        float ds = __shfl_sync(gmask, v.w, 2, 4);
        acc.x += ds * v.x; acc.y += ds * v.y;
        acc.z += ds * v.z; acc.w += ds * v.w;
        k = 1;
    }
    int pairs = (cnt - k) >> 1;
    const int2* ep = reinterpret_cast<const int2*>(&g_esrc[beg + k]);
#pragma unroll 2
    for (int p = 0; p < pairs; p++) {
        int2 ss = __ldg(&ep[p]);
        float4 v0 = make_float4(0.f, 0.f, 0.f, 0.f);
        float4 v1 = make_float4(0.f, 0.f, 0.f, 0.f);
        if (lane < 3) {
            v0 = __ldg(reinterpret_cast<const float4*>(&g_Y1[ss.x * OUTP]) + lane);
            v1 = __ldg(reinterpret_cast<const float4*>(&g_Y1[ss.y * OUTP]) + lane);
        }
        float ds0 = __shfl_sync(gmask, v0.w, 2, 4);
        float ds1 = __shfl_sync(gmask, v1.w, 2, 4);
        acc.x += ds0 * v0.x + ds1 * v1.x;
        acc.y += ds0 * v0.y + ds1 * v1.y;
        acc.z += ds0 * v0.z + ds1 * v1.z;
        acc.w += ds0 * v0.w + ds1 * v1.w;
    }
    k += pairs * 2;
    if (k < cnt) {
        int s = __ldg(&g_esrc[beg + k]);
        float4 v = make_float4(0.f, 0.f, 0.f, 0.f);
        if (lane < 3) v = __ldg(reinterpret_cast<const float4*>(&g_Y1[s * OUTP]) + lane);
        float ds = __shfl_sync(gmask, v.w, 2, 4);
        acc.x += ds * v.x; acc.y += ds * v.y;
        acc.z += ds * v.z; acc.w += ds * v.w;
    }
    if (lane < 3) {
        float4 y1 = *(reinterpret_cast<const float4*>(&g_Y1[node * OUTP]) + lane);
        float4 y;
        y.x = dd * (dd * y1.x + acc.x);
        y.y = dd * (dd * y1.y + acc.y);
        y.z = dd * (dd * y1.z + acc.z);
        y.w = dd * (dd * y1.w + acc.w);
        *(reinterpret_cast<float4*>(&g_Y2[node * OUTP]) + lane) = y;
    } else {
        g_cnt[node] = 0;                 // replay invariant
    }
}

// 5: 2 threads/node; each computes 20 output columns (measured better than 1/node).
//    emb_b = relu(Y2 + s*c + b2);  out = [emb_a, emb_b] @ Wc + bc
__global__ void k_final(const float* __restrict__ emb_a, const float* __restrict__ b2,
                        const float* __restrict__ Wc, const float* __restrict__ bc,
                        float* __restrict__ out, int n) {
    __shared__ float wsm[CDIM * NCLASS];
    __shared__ float bsm[NCLASS];
    __shared__ float csm[OUTH];
    __shared__ float b2sm[OUTH];
    for (int t = threadIdx.x; t < CDIM * NCLASS; t += blockDim.x) wsm[t] = Wc[t];
    if (threadIdx.x < NCLASS) bsm[threadIdx.x] = bc[threadIdx.x];
    if (threadIdx.x < OUTH) { csm[threadIdx.x] = g_c[threadIdx.x]; b2sm[threadIdx.x] = b2[threadIdx.x]; }
    __syncthreads();
    int tid  = blockIdx.x * blockDim.x + threadIdx.x;
    int node = tid >> 1;
    int half = tid & 1;
    if (node >= n) return;
    int colb = half * 20;

    float acc[20];
#pragma unroll
    for (int q = 0; q < 20; q++) acc[q] = bsm[colb + q];

    const float4* ea = reinterpret_cast<const float4*>(&emb_a[(size_t)node * NCLASS]);
#pragma unroll
    for (int m4 = 0; m4 < NCLASS / 4; m4++) {
        float4 v = __ldg(&ea[m4]);
        float vv[4] = {v.x, v.y, v.z, v.w};
#pragma unroll
        for (int c = 0; c < 4; c++) {
            float a = vv[c];
            int m = m4 * 4 + c;
#pragma unroll
            for (int q = 0; q < 20; q++) acc[q] += a * wsm[m * NCLASS + colb + q];
        }
    }

    float di = g_dinv[node];
    float s = di * (di + g_sdin[node]);
#pragma unroll
    for (int j = 0; j < OUTH; j++) {
        float h = g_Y2[(size_t)node * OUTP + j] + s * csm[j] + b2sm[j];
        h = fmaxf(h, 0.0f);
#pragma unroll
        for (int q = 0; q < 20; q++) acc[q] += h * wsm[(NCLASS + j) * NCLASS + colb + q];
    }

    float4* op = reinterpret_cast<float4*>(&out[(size_t)node * NCLASS + colb]);
#pragma unroll
    for (int q4 = 0; q4 < 5; q4++)
        op[q4] = make_float4(acc[q4 * 4], acc[q4 * 4 + 1], acc[q4 * 4 + 2], acc[q4 * 4 + 3]);
}

// ---------------- launch ----------------
extern "C" void kernel_launch(void* const* d_in, const int* in_sizes, int n_in,
                              void* d_out, int out_size) {
    const float* x     = (const float*)d_in[0];
    const int*   ei    = (const int*)d_in[1];     // int32 (JAX x64 disabled)
    const float* emb_a = (const float*)d_in[2];
    const float* W1    = (const float*)d_in[3];
    const float* b1    = (const float*)d_in[4];
    const float* W2    = (const float*)d_in[5];
    const float* b2    = (const float*)d_in[6];
    const float* Wc    = (const float*)d_in[7];
    const float* bc    = (const float*)d_in[8];
    float* out = (float*)d_out;

    int n  = in_sizes[0] / INH;   // 100000
    int e  = in_sizes[1] / 2;     // 1600000
    int nh = in_sizes[4];         // 256

    const int TB = 256;
    int nblk = (n + 1023) / 1024;             // 98
    k_deg    <<<(e / 4 + TB - 1) / TB, TB>>>(ei + e, e);                 // 0
    k_scanM  <<<nblk, 256>>>(x, W1, W2, b1, nh, n);                      // 1
    k_scatter<<<(e / 4 + TB - 1) / TB, TB>>>(ei, e);                     // 2
    k_agg0   <<<(n * 4 + TB - 1) / TB, TB>>>(n);                         // 3 <- ncu
    k_agg1   <<<(n * 4 + TB - 1) / TB, TB>>>(n);                         // 4
    k_final  <<<(n * 2 + TB - 1) / TB, TB>>>(emb_a, b2, Wc, bc, out, n); // 5
}